// round 14
// baseline (speedup 1.0000x reference)
#include <cuda_runtime.h>
#include <cuda_fp16.h>
#include <cstdint>

#define HD 64
#define NMAX 300000
#define EMAX 4800000

typedef unsigned long long ull;

// Scratch — device globals (no cudaMalloc allowed).
__device__ float  g_x[(size_t)NMAX * HD];    // encoded / layer-out features (fp32)
__device__ float  g_y[(size_t)NMAX * HD];    // layer-1 output (fp32)
__device__ __half g_xh[(size_t)NMAX * HD];   // fp16 shadow of current features (gather path)
__device__ __half g_aggh[(size_t)NMAX * HD]; // neighbor-mean buffer (fp16)
__device__ int    g_deg[NMAX];               // in-degree
__device__ int    g_excl[NMAX];              // block-local exclusive scan
__device__ int    g_off[NMAX + 1];           // CSR offsets
__device__ int    g_cur[NMAX];               // bucket cursors
__device__ int    g_bsum[512];               // per-block sums for scan
__device__ int    g_nbr[EMAX];               // CSR neighbor (src) ids

// ---------------------------------------------------------------------------
// packed f32x2 helpers (sm_103a FFMA2 — only reachable via PTX)
// ---------------------------------------------------------------------------
__device__ __forceinline__ ull fma2(ull a, ull b, ull c) {
    ull d;
    asm("fma.rn.f32x2 %0, %1, %2, %3;" : "=l"(d) : "l"(a), "l"(b), "l"(c));
    return d;
}
__device__ __forceinline__ ull pack2(float x) {
    ull d;
    asm("mov.b64 %0, {%1, %1};" : "=l"(d) : "f"(x));
    return d;
}
__device__ __forceinline__ void unpack2(ull v, float& lo, float& hi) {
    asm("mov.b64 {%0, %1}, %2;" : "=f"(lo), "=f"(hi) : "l"(v));
}
// pack 8 floats -> 8 fp16 in one 16B store payload
__device__ __forceinline__ void pack_half8(const float* f, uint4& out) {
    __half2 h0 = __floats2half2_rn(f[0], f[1]);
    __half2 h1 = __floats2half2_rn(f[2], f[3]);
    __half2 h2 = __floats2half2_rn(f[4], f[5]);
    __half2 h3 = __floats2half2_rn(f[6], f[7]);
    out.x = *reinterpret_cast<unsigned*>(&h0);
    out.y = *reinterpret_cast<unsigned*>(&h1);
    out.z = *reinterpret_cast<unsigned*>(&h2);
    out.w = *reinterpret_cast<unsigned*>(&h3);
}
// load 4 fp16 (8B) -> float4
__device__ __forceinline__ float4 load_half4(const __half* p) {
    uint2 raw = __ldg(reinterpret_cast<const uint2*>(p));
    __half2 h0 = *reinterpret_cast<__half2*>(&raw.x);
    __half2 h1 = *reinterpret_cast<__half2*>(&raw.y);
    float2 a = __half22float2(h0);
    float2 c = __half22float2(h1);
    return make_float4(a.x, a.y, c.x, c.y);
}

// ---------------------------------------------------------------------------
// zero fill (16B granularity)
// ---------------------------------------------------------------------------
__global__ void zero_kernel(float4* __restrict__ p, int n4) {
    int i = blockIdx.x * blockDim.x + threadIdx.x;
    if (i < n4) p[i] = make_float4(0.f, 0.f, 0.f, 0.f);
}

// ---------------------------------------------------------------------------
// in-degree histogram
// ---------------------------------------------------------------------------
__global__ void degree_kernel(const int* __restrict__ dst, int* __restrict__ deg, int E) {
    int i = blockIdx.x * blockDim.x + threadIdx.x;
    if (i < E) atomicAdd(deg + __ldg(dst + i), 1);
}

// ---------------------------------------------------------------------------
// prefix scan (3 kernels): 1024 elems/block
// ---------------------------------------------------------------------------
__global__ __launch_bounds__(256) void scan1_kernel(const int* __restrict__ deg,
                                                    int* __restrict__ excl,
                                                    int* __restrict__ bsum, int n) {
    __shared__ int wsum[8];
    int t = threadIdx.x;
    int base = blockIdx.x * 1024 + t * 4;
    int v[4];
#pragma unroll
    for (int k = 0; k < 4; k++) v[k] = (base + k < n) ? deg[base + k] : 0;
    int tsum = v[0] + v[1] + v[2] + v[3];
    int lane = t & 31, w = t >> 5;
    int x = tsum;
#pragma unroll
    for (int o = 1; o < 32; o <<= 1) {
        int y = __shfl_up_sync(~0u, x, o);
        if (lane >= o) x += y;
    }
    if (lane == 31) wsum[w] = x;
    __syncthreads();
    if (t < 8) {
        int y = wsum[t];
#pragma unroll
        for (int o = 1; o < 8; o <<= 1) {
            int z = __shfl_up_sync(0xff, y, o);
            if (t >= o) y += z;
        }
        wsum[t] = y;
    }
    __syncthreads();
    int run = (w > 0 ? wsum[w - 1] : 0) + x - tsum;  // exclusive over threads
#pragma unroll
    for (int k = 0; k < 4; k++) {
        if (base + k < n) excl[base + k] = run;
        run += v[k];
    }
    if (t == 0) bsum[blockIdx.x] = wsum[7];
}

__global__ __launch_bounds__(512) void scan2_kernel(int* __restrict__ bsum, int nb) {
    __shared__ int wsum[16];
    int t = threadIdx.x;
    int v = (t < nb) ? bsum[t] : 0;
    int lane = t & 31, w = t >> 5;
    int x = v;
#pragma unroll
    for (int o = 1; o < 32; o <<= 1) {
        int y = __shfl_up_sync(~0u, x, o);
        if (lane >= o) x += y;
    }
    if (lane == 31) wsum[w] = x;
    __syncthreads();
    if (t < 16) {
        int y = wsum[t];
#pragma unroll
        for (int o = 1; o < 16; o <<= 1) {
            int z = __shfl_up_sync(0xffff, y, o);
            if (t >= o) y += z;
        }
        wsum[t] = y;
    }
    __syncthreads();
    int excl = (w > 0 ? wsum[w - 1] : 0) + x - v;
    if (t < nb) bsum[t] = excl;
}

__global__ void scan3_kernel(const int* __restrict__ excl, const int* __restrict__ bsum,
                             int* __restrict__ off, int* __restrict__ cur, int n, int E) {
    int i = blockIdx.x * blockDim.x + threadIdx.x;
    if (i < n) {
        int o = excl[i] + bsum[i >> 10];
        off[i] = o;
        cur[i] = o;
    }
    if (i == 0) off[n] = E;
}

// ---------------------------------------------------------------------------
// bucket permute: nbr sorted by dst
// ---------------------------------------------------------------------------
__global__ void bucket_kernel(const int* __restrict__ src, const int* __restrict__ dst,
                              int* __restrict__ cur, int* __restrict__ nbr, int E) {
    int i = blockIdx.x * blockDim.x + threadIdx.x;
    if (i < E) {
        int p = atomicAdd(cur + __ldg(dst + i), 1);
        nbr[p] = __ldg(src + i);
    }
}

// ---------------------------------------------------------------------------
// gather aggregation over fp16 features: mean over neighbors, 1 warp/node.
// lane owns 2 columns -> half2 (4B); one neighbor row = 128B = ONE L2 line.
// fp32 accumulation; mean stored as fp16.
// ---------------------------------------------------------------------------
__global__ __launch_bounds__(256) void agg_kernel(const __half* __restrict__ xh,
                                                  const int* __restrict__ off,
                                                  const int* __restrict__ nbr,
                                                  __half* __restrict__ mean, int N) {
    int warp = (blockIdx.x * blockDim.x + threadIdx.x) >> 5;
    if (warp >= N) return;
    int lane = threadIdx.x & 31;
    int s0 = __ldg(off + warp), s1 = __ldg(off + warp + 1);
    float ax = 0.f, ay = 0.f;
    const __half* xl = xh + lane * 2;
    int j = s0;
    for (; j + 32 <= s1; j += 32) {
        int myid = __ldg(nbr + j + lane);
#pragma unroll
        for (int k = 0; k < 32; k++) {
            int s = __shfl_sync(~0u, myid, k);
            __half2 h = *reinterpret_cast<const __half2*>(xl + (size_t)s * HD);
            float2 v = __half22float2(h);
            ax += v.x;
            ay += v.y;
        }
    }
    if (j < s1) {
        int cnt = s1 - j;
        int myid = (lane < cnt) ? __ldg(nbr + j + lane) : 0;
        for (int k = 0; k < cnt; k++) {
            int s = __shfl_sync(~0u, myid, k);
            __half2 h = *reinterpret_cast<const __half2*>(xl + (size_t)s * HD);
            float2 v = __half22float2(h);
            ax += v.x;
            ay += v.y;
        }
    }
    float inv = 1.0f / (float)max(s1 - s0, 1);
    __half2 o = __floats2half2_rn(ax * inv, ay * inv);
    *reinterpret_cast<__half2*>(mean + (size_t)warp * HD + lane * 2) = o;
}

// ---------------------------------------------------------------------------
// per-type encoder, register-tiled: 4 rows x 8 cols per thread.
// Writes fp32 output AND fp16 shadow directly.
// ---------------------------------------------------------------------------
template <int FIN>
__global__ __launch_bounds__(256) void encode_kernel(
    const float* __restrict__ x, const float* __restrict__ W,
    const float* __restrict__ b, float* __restrict__ out,
    __half* __restrict__ outh, int n) {
    __shared__ __align__(16) float sW[FIN * HD];
    __shared__ __align__(16) float sb[HD];
    for (int i = threadIdx.x; i < FIN * HD; i += 256) sW[i] = W[i];
    if (threadIdx.x < HD) sb[threadIdx.x] = b[threadIdx.x];
    __syncthreads();
    int cg = threadIdx.x & 7, rg = threadIdx.x >> 3;
    int row0 = blockIdx.x * 128 + rg * 4;
    int col0 = cg * 8;
    if (row0 >= n) return;

    ull acc[4][4];
    {
        const ull* sbp = reinterpret_cast<const ull*>(sb + col0);
#pragma unroll
        for (int i = 0; i < 4; i++)
#pragma unroll
            for (int c = 0; c < 4; c++) acc[i][c] = sbp[c];
    }
    int r[4];
#pragma unroll
    for (int i = 0; i < 4; i++) r[i] = min(row0 + i, n - 1);

#pragma unroll 1
    for (int kc = 0; kc < FIN / 4; kc++) {
        float4 xv[4];
#pragma unroll
        for (int i = 0; i < 4; i++)
            xv[i] = __ldg(reinterpret_cast<const float4*>(x + (size_t)r[i] * FIN + kc * 4));
#pragma unroll
        for (int kk = 0; kk < 4; kk++) {
            int k = kc * 4 + kk;
            const ulonglong2* pw =
                reinterpret_cast<const ulonglong2*>(sW + k * HD + col0);
            ulonglong2 w0 = pw[0], w1 = pw[1];
            float xk[4] = {0, 0, 0, 0};
#pragma unroll
            for (int i = 0; i < 4; i++)
                xk[i] = reinterpret_cast<const float*>(&xv[i])[kk];
#pragma unroll
            for (int i = 0; i < 4; i++) {
                ull xk2 = pack2(xk[i]);
                acc[i][0] = fma2(xk2, w0.x, acc[i][0]);
                acc[i][1] = fma2(xk2, w0.y, acc[i][1]);
                acc[i][2] = fma2(xk2, w1.x, acc[i][2]);
                acc[i][3] = fma2(xk2, w1.y, acc[i][3]);
            }
        }
    }
#pragma unroll
    for (int i = 0; i < 4; i++) {
        if (row0 + i < n) {
            float f[8];
            unpack2(acc[i][0], f[0], f[1]);
            unpack2(acc[i][1], f[2], f[3]);
            unpack2(acc[i][2], f[4], f[5]);
            unpack2(acc[i][3], f[6], f[7]);
            float4* o = reinterpret_cast<float4*>(out + (size_t)(row0 + i) * HD + col0);
            o[0] = make_float4(f[0], f[1], f[2], f[3]);
            o[1] = make_float4(f[4], f[5], f[6], f[7]);
            uint4 hp;
            pack_half8(f, hp);
            *reinterpret_cast<uint4*>(outh + (size_t)(row0 + i) * HD + col0) = hp;
        }
    }
}

// ---------------------------------------------------------------------------
// SAGE combine (layer 1): out = relu( mean @ Wl + x @ Wr + b )
// mean read as fp16; writes fp32 output + fp16 shadow.
// ---------------------------------------------------------------------------
__global__ __launch_bounds__(256) void sage_combine_kernel(
    const float* __restrict__ x, const __half* __restrict__ mean,
    const float* __restrict__ Wl, const float* __restrict__ Wr,
    const float* __restrict__ b, float* __restrict__ out,
    __half* __restrict__ outh, int n) {
    __shared__ __align__(16) float sWl[HD * HD];
    __shared__ __align__(16) float sWr[HD * HD];
    __shared__ __align__(16) float sb[HD];
    for (int i = threadIdx.x; i < HD * HD; i += 256) {
        sWl[i] = Wl[i];
        sWr[i] = Wr[i];
    }
    if (threadIdx.x < HD) sb[threadIdx.x] = b[threadIdx.x];
    __syncthreads();
    int cg = threadIdx.x & 7, rg = threadIdx.x >> 3;
    int row0 = blockIdx.x * 128 + rg * 4;
    int col0 = cg * 8;
    if (row0 >= n) return;

    ull acc[4][4];
    {
        const ull* sbp = reinterpret_cast<const ull*>(sb + col0);
#pragma unroll
        for (int i = 0; i < 4; i++)
#pragma unroll
            for (int c = 0; c < 4; c++) acc[i][c] = sbp[c];
    }
    int r[4];
#pragma unroll
    for (int i = 0; i < 4; i++) r[i] = min(row0 + i, n - 1);

#pragma unroll 1
    for (int kc = 0; kc < 16; kc++) {
        float4 xv[4], mv[4];
#pragma unroll
        for (int i = 0; i < 4; i++) {
            xv[i] = __ldg(reinterpret_cast<const float4*>(x + (size_t)r[i] * HD + kc * 4));
            mv[i] = load_half4(mean + (size_t)r[i] * HD + kc * 4);
        }
#pragma unroll
        for (int kk = 0; kk < 4; kk++) {
            int k = kc * 4 + kk;
            const ulonglong2* pl =
                reinterpret_cast<const ulonglong2*>(sWl + k * HD + col0);
            const ulonglong2* pr =
                reinterpret_cast<const ulonglong2*>(sWr + k * HD + col0);
            ulonglong2 l0 = pl[0], l1 = pl[1];
            ulonglong2 r0 = pr[0], r1 = pr[1];
#pragma unroll
            for (int i = 0; i < 4; i++) {
                ull mk2 = pack2(reinterpret_cast<const float*>(&mv[i])[kk]);
                ull xk2 = pack2(reinterpret_cast<const float*>(&xv[i])[kk]);
                acc[i][0] = fma2(mk2, l0.x, acc[i][0]);
                acc[i][0] = fma2(xk2, r0.x, acc[i][0]);
                acc[i][1] = fma2(mk2, l0.y, acc[i][1]);
                acc[i][1] = fma2(xk2, r0.y, acc[i][1]);
                acc[i][2] = fma2(mk2, l1.x, acc[i][2]);
                acc[i][2] = fma2(xk2, r1.x, acc[i][2]);
                acc[i][3] = fma2(mk2, l1.y, acc[i][3]);
                acc[i][3] = fma2(xk2, r1.y, acc[i][3]);
            }
        }
    }
#pragma unroll
    for (int i = 0; i < 4; i++) {
        if (row0 + i < n) {
            float f[8];
            unpack2(acc[i][0], f[0], f[1]);
            unpack2(acc[i][1], f[2], f[3]);
            unpack2(acc[i][2], f[4], f[5]);
            unpack2(acc[i][3], f[6], f[7]);
#pragma unroll
            for (int c = 0; c < 8; c++) f[c] = fmaxf(f[c], 0.f);
            float4* o = reinterpret_cast<float4*>(out + (size_t)(row0 + i) * HD + col0);
            o[0] = make_float4(f[0], f[1], f[2], f[3]);
            o[1] = make_float4(f[4], f[5], f[6], f[7]);
            uint4 hp;
            pack_half8(f, hp);
            *reinterpret_cast<uint4*>(outh + (size_t)(row0 + i) * HD + col0) = hp;
        }
    }
}

// ---------------------------------------------------------------------------
// FUSED combine2 + classifier:
//   rows = relu( mean @ W2l + y @ W2r + b2 )    (staged in SMEM only)
//   h    = relu( rows @ Wc1 + bc1 )
//   out  = h @ Wc2 + bc2
// Dynamic SMEM layout (floats):
//   [0..4095]    sWl          (combine phase; later overlaid)
//   [4096..8191] sWr
//   [8192..8255] sb
//   [8256..+8704) sRow (128 x 68)
//   overlay after combine:  sW1[0..2047], sb1[2048..2079], sW2[2080..2143],
//                           sb2[2144..2145], sh[2160..+4224) (128 x 33)
// ---------------------------------------------------------------------------
#define FUSED_SMEM ((8256 + 128 * 68) * 4)

__global__ __launch_bounds__(256) void combine2_classify_kernel(
    const float* __restrict__ x, const __half* __restrict__ mean,
    const float* __restrict__ Wl, const float* __restrict__ Wr,
    const float* __restrict__ b,
    const float* __restrict__ Wc1, const float* __restrict__ bc1,
    const float* __restrict__ Wc2, const float* __restrict__ bc2,
    float* __restrict__ out, int n) {
    extern __shared__ __align__(16) float sm[];
    float* sWl = sm;
    float* sWr = sm + 4096;
    float* sb = sm + 8192;
    float* sRow = sm + 8256;  // 128 x 68

    int tid = threadIdx.x;
    for (int i = tid; i < 4096; i += 256) {
        sWl[i] = Wl[i];
        sWr[i] = Wr[i];
    }
    if (tid < 64) sb[tid] = b[tid];
    __syncthreads();

    // ---- combine phase: 4 rows x 8 cols per thread -> sRow
    int cg = tid & 7, rg = tid >> 3;
    int row0 = blockIdx.x * 128 + rg * 4;
    int col0 = cg * 8;
    if (row0 < n) {
        ull acc[4][4];
        {
            const ull* sbp = reinterpret_cast<const ull*>(sb + col0);
#pragma unroll
            for (int i = 0; i < 4; i++)
#pragma unroll
                for (int c = 0; c < 4; c++) acc[i][c] = sbp[c];
        }
        int r[4];
#pragma unroll
        for (int i = 0; i < 4; i++) r[i] = min(row0 + i, n - 1);

#pragma unroll 1
        for (int kc = 0; kc < 16; kc++) {
            float4 xv[4], mv[4];
#pragma unroll
            for (int i = 0; i < 4; i++) {
                xv[i] = __ldg(reinterpret_cast<const float4*>(x + (size_t)r[i] * HD + kc * 4));
                mv[i] = load_half4(mean + (size_t)r[i] * HD + kc * 4);
            }
#pragma unroll
            for (int kk = 0; kk < 4; kk++) {
                int k = kc * 4 + kk;
                const ulonglong2* pl =
                    reinterpret_cast<const ulonglong2*>(sWl + k * HD + col0);
                const ulonglong2* pr =
                    reinterpret_cast<const ulonglong2*>(sWr + k * HD + col0);
                ulonglong2 l0 = pl[0], l1 = pl[1];
                ulonglong2 r0 = pr[0], r1 = pr[1];
#pragma unroll
                for (int i = 0; i < 4; i++) {
                    ull mk2 = pack2(reinterpret_cast<const float*>(&mv[i])[kk]);
                    ull xk2 = pack2(reinterpret_cast<const float*>(&xv[i])[kk]);
                    acc[i][0] = fma2(mk2, l0.x, acc[i][0]);
                    acc[i][0] = fma2(xk2, r0.x, acc[i][0]);
                    acc[i][1] = fma2(mk2, l0.y, acc[i][1]);
                    acc[i][1] = fma2(xk2, r0.y, acc[i][1]);
                    acc[i][2] = fma2(mk2, l1.x, acc[i][2]);
                    acc[i][2] = fma2(xk2, r1.x, acc[i][2]);
                    acc[i][3] = fma2(mk2, l1.y, acc[i][3]);
                    acc[i][3] = fma2(xk2, r1.y, acc[i][3]);
                }
            }
        }
#pragma unroll
        for (int i = 0; i < 4; i++) {
            float f[8];
            unpack2(acc[i][0], f[0], f[1]);
            unpack2(acc[i][1], f[2], f[3]);
            unpack2(acc[i][2], f[4], f[5]);
            unpack2(acc[i][3], f[6], f[7]);
            float* dstp = sRow + (rg * 4 + i) * 68 + col0;
#pragma unroll
            for (int c = 0; c < 8; c++) dstp[c] = fmaxf(f[c], 0.f);
        }
    }
    __syncthreads();

    // ---- overlay classifier weights onto dead Wl/Wr region
    float* sW1 = sm;          // 2048
    float* sb1 = sm + 2048;   // 32
    float* sW2 = sm + 2080;   // 64
    float* sb2v = sm + 2144;  // 2
    float* sh = sm + 2160;    // 128 x 33
    for (int i = tid; i < 2048; i += 256) sW1[i] = Wc1[i];
    if (tid < 64) sW2[tid] = Wc2[tid];
    if (tid < 32) sb1[tid] = bc1[tid];
    if (tid < 2) sb2v[tid] = bc2[tid];
    __syncthreads();

    // ---- classify phase 1: 2 rows x 8 hidden cols per thread
    {
        int ccg = tid & 3, crg = tid >> 2;  // 4 colgroups x 64 rowgroups
        int lrow0 = crg * 2;
        int ccol0 = ccg * 8;
        ull acc[2][4];
        {
            const ull* sbp = reinterpret_cast<const ull*>(sb1 + ccol0);
#pragma unroll
            for (int i = 0; i < 2; i++)
#pragma unroll
                for (int c = 0; c < 4; c++) acc[i][c] = sbp[c];
        }
#pragma unroll 1
        for (int kc = 0; kc < 16; kc++) {
            float xv[2][4];
#pragma unroll
            for (int i = 0; i < 2; i++) {
                const float* rp = sRow + (lrow0 + i) * 68 + kc * 4;
#pragma unroll
                for (int c = 0; c < 4; c++) xv[i][c] = rp[c];
            }
#pragma unroll
            for (int kk = 0; kk < 4; kk++) {
                int k = kc * 4 + kk;
                const ulonglong2* pw =
                    reinterpret_cast<const ulonglong2*>(sW1 + k * 32 + ccol0);
                ulonglong2 w0 = pw[0], w1 = pw[1];
#pragma unroll
                for (int i = 0; i < 2; i++) {
                    ull xk2 = pack2(xv[i][kk]);
                    acc[i][0] = fma2(xk2, w0.x, acc[i][0]);
                    acc[i][1] = fma2(xk2, w0.y, acc[i][1]);
                    acc[i][2] = fma2(xk2, w1.x, acc[i][2]);
                    acc[i][3] = fma2(xk2, w1.y, acc[i][3]);
                }
            }
        }
#pragma unroll
        for (int i = 0; i < 2; i++) {
            float h[8];
            unpack2(acc[i][0], h[0], h[1]);
            unpack2(acc[i][1], h[2], h[3]);
            unpack2(acc[i][2], h[4], h[5]);
            unpack2(acc[i][3], h[6], h[7]);
            float* dstp = sh + (lrow0 + i) * 33 + ccol0;
#pragma unroll
            for (int c = 0; c < 8; c++) dstp[c] = fmaxf(h[c], 0.f);
        }
    }
    __syncthreads();

    // ---- classify phase 2: thread-per-row (first 128 threads)
    int row = blockIdx.x * 128 + tid;
    if (tid < 128 && row < n) {
        const float* hr = sh + tid * 33;
        float o0 = sb2v[0], o1 = sb2v[1];
#pragma unroll
        for (int j = 0; j < 32; j++) {
            float hv = hr[j];
            o0 += hv * sW2[j * 2 + 0];
            o1 += hv * sW2[j * 2 + 1];
        }
        out[(size_t)row * 2 + 0] = o0;
        out[(size_t)row * 2 + 1] = o1;
    }
}

// ---------------------------------------------------------------------------
// launch (forked capture: encoders on side stream ∥ CSR build on main)
// ---------------------------------------------------------------------------
extern "C" void kernel_launch(void* const* d_in, const int* in_sizes, int n_in,
                              void* d_out, int out_size) {
    const float* x_ind = (const float*)d_in[0];
    const float* x_com = (const float*)d_in[1];
    const float* x_tru = (const float*)d_in[2];
    const int*   ei    = (const int*)d_in[3];
    const float* W_ind = (const float*)d_in[4];
    const float* b_ind = (const float*)d_in[5];
    const float* W_com = (const float*)d_in[6];
    const float* b_com = (const float*)d_in[7];
    const float* W_tru = (const float*)d_in[8];
    const float* b_tru = (const float*)d_in[9];
    const float* W1l = (const float*)d_in[10];
    const float* W1r = (const float*)d_in[11];
    const float* b1  = (const float*)d_in[12];
    const float* W2l = (const float*)d_in[13];
    const float* W2r = (const float*)d_in[14];
    const float* b2  = (const float*)d_in[15];
    const float* Wc1 = (const float*)d_in[16];
    const float* bc1 = (const float*)d_in[17];
    const float* Wc2 = (const float*)d_in[18];
    const float* bc2 = (const float*)d_in[19];

    int n_ind = in_sizes[0] / 32;
    int n_com = in_sizes[1] / 48;
    int n_tru = in_sizes[2] / 24;
    int N = n_ind + n_com + n_tru;
    int E = in_sizes[3] / 2;
    const int* src = ei;
    const int* dst = ei + E;

    float *gx, *gy;
    __half *gxh, *gaggh;
    int *gdeg, *gexcl, *goff, *gcur, *gbsum, *gnbr;
    cudaGetSymbolAddress((void**)&gx, g_x);
    cudaGetSymbolAddress((void**)&gy, g_y);
    cudaGetSymbolAddress((void**)&gxh, g_xh);
    cudaGetSymbolAddress((void**)&gaggh, g_aggh);
    cudaGetSymbolAddress((void**)&gdeg, g_deg);
    cudaGetSymbolAddress((void**)&gexcl, g_excl);
    cudaGetSymbolAddress((void**)&goff, g_off);
    cudaGetSymbolAddress((void**)&gcur, g_cur);
    cudaGetSymbolAddress((void**)&gbsum, g_bsum);
    cudaGetSymbolAddress((void**)&gnbr, g_nbr);

    // one-time stream/event setup (first call is the uncaptured correctness run)
    static cudaStream_t s2 = nullptr;
    static cudaEvent_t evFork = nullptr, evEnc = nullptr;
    if (s2 == nullptr) {
        cudaStreamCreateWithFlags(&s2, cudaStreamNonBlocking);
        cudaEventCreateWithFlags(&evFork, cudaEventDisableTiming);
        cudaEventCreateWithFlags(&evEnc, cudaEventDisableTiming);
        cudaFuncSetAttribute(combine2_classify_kernel,
                             cudaFuncAttributeMaxDynamicSharedMemorySize, FUSED_SMEM);
    }

    // ---- fork: side stream joins the capture graph
    cudaEventRecord(evFork, 0);
    cudaStreamWaitEvent(s2, evFork, 0);

    // ---- main stream: CSR build
    int nInt4 = (N + 3) / 4;
    zero_kernel<<<(nInt4 + 255) / 256, 256>>>((float4*)gdeg, nInt4);
    degree_kernel<<<(E + 255) / 256, 256>>>(dst, gdeg, E);
    int nb = (N + 1023) / 1024;
    scan1_kernel<<<nb, 256>>>(gdeg, gexcl, gbsum, N);

    // ---- side stream: encoders (write fp32 + fp16 shadow directly)
    encode_kernel<48><<<(n_com + 127) / 128, 256, 0, s2>>>(
        x_com, W_com, b_com, gx + (size_t)n_ind * HD, gxh + (size_t)n_ind * HD, n_com);
    encode_kernel<32><<<(n_ind + 127) / 128, 256, 0, s2>>>(
        x_ind, W_ind, b_ind, gx, gxh, n_ind);
    encode_kernel<24><<<(n_tru + 127) / 128, 256, 0, s2>>>(
        x_tru, W_tru, b_tru, gx + (size_t)(n_ind + n_com) * HD,
        gxh + (size_t)(n_ind + n_com) * HD, n_tru);
    cudaEventRecord(evEnc, s2);

    // ---- main stream: rest of CSR build
    scan2_kernel<<<1, 512>>>(gbsum, nb);
    scan3_kernel<<<(N + 255) / 256, 256>>>(gexcl, gbsum, goff, gcur, N, E);
    bucket_kernel<<<(E + 255) / 256, 256>>>(src, dst, gcur, gnbr, E);

    // ---- join: layers need both encoders and CSR
    cudaStreamWaitEvent(0, evEnc, 0);

    // ---- SAGE layer 1: gather fp16 -> fp16 mean; combine -> g_y (+ shadow)
    agg_kernel<<<(N * 32 + 255) / 256, 256>>>(gxh, goff, gnbr, gaggh, N);
    sage_combine_kernel<<<(N + 127) / 128, 256>>>(gx, gaggh, W1l, W1r, b1, gy, gxh, N);

    // ---- SAGE layer 2 (fused with classifier) -> d_out
    agg_kernel<<<(N * 32 + 255) / 256, 256>>>(gxh, goff, gnbr, gaggh, N);
    combine2_classify_kernel<<<(N + 127) / 128, 256, FUSED_SMEM>>>(
        gy, gaggh, W2l, W2r, b2, Wc1, bc1, Wc2, bc2, (float*)d_out, N);
}

// round 15
// speedup vs baseline: 1.0376x; 1.0376x over previous
#include <cuda_runtime.h>
#include <cuda_fp16.h>
#include <cstdint>

#define HD 64
#define NMAX 300000
#define EMAX 4800000

typedef unsigned long long ull;

// Scratch — device globals (no cudaMalloc allowed).
__device__ float  g_x[(size_t)NMAX * HD];    // encoded / layer-out features (fp32)
__device__ float  g_y[(size_t)NMAX * HD];    // layer-1 output (fp32)
__device__ __half g_xh[(size_t)NMAX * HD];   // fp16 shadow of current features (gather path)
__device__ __half g_aggh[(size_t)NMAX * HD]; // neighbor-mean buffer (fp16)
__device__ int    g_deg[NMAX];               // in-degree
__device__ int    g_excl[NMAX];              // block-local exclusive scan
__device__ int    g_off[NMAX + 1];           // CSR offsets
__device__ int    g_cur[NMAX];               // bucket cursors
__device__ int    g_bsum[512];               // per-block sums for scan
__device__ int    g_nbr[EMAX];               // CSR neighbor (src) ids

// ---------------------------------------------------------------------------
// packed f32x2 helpers (sm_103a FFMA2 — only reachable via PTX)
// ---------------------------------------------------------------------------
__device__ __forceinline__ ull fma2(ull a, ull b, ull c) {
    ull d;
    asm("fma.rn.f32x2 %0, %1, %2, %3;" : "=l"(d) : "l"(a), "l"(b), "l"(c));
    return d;
}
__device__ __forceinline__ ull pack2(float x) {
    ull d;
    asm("mov.b64 %0, {%1, %1};" : "=l"(d) : "f"(x));
    return d;
}
__device__ __forceinline__ void unpack2(ull v, float& lo, float& hi) {
    asm("mov.b64 {%0, %1}, %2;" : "=f"(lo), "=f"(hi) : "l"(v));
}
// pack 8 floats -> 8 fp16 in one 16B store payload
__device__ __forceinline__ void pack_half8(const float* f, uint4& out) {
    __half2 h0 = __floats2half2_rn(f[0], f[1]);
    __half2 h1 = __floats2half2_rn(f[2], f[3]);
    __half2 h2 = __floats2half2_rn(f[4], f[5]);
    __half2 h3 = __floats2half2_rn(f[6], f[7]);
    out.x = *reinterpret_cast<unsigned*>(&h0);
    out.y = *reinterpret_cast<unsigned*>(&h1);
    out.z = *reinterpret_cast<unsigned*>(&h2);
    out.w = *reinterpret_cast<unsigned*>(&h3);
}
// load 4 fp16 (8B) -> float4
__device__ __forceinline__ float4 load_half4(const __half* p) {
    uint2 raw = __ldg(reinterpret_cast<const uint2*>(p));
    __half2 h0 = *reinterpret_cast<__half2*>(&raw.x);
    __half2 h1 = *reinterpret_cast<__half2*>(&raw.y);
    float2 a = __half22float2(h0);
    float2 c = __half22float2(h1);
    return make_float4(a.x, a.y, c.x, c.y);
}

// ---------------------------------------------------------------------------
// zero fill (16B granularity)
// ---------------------------------------------------------------------------
__global__ void zero_kernel(float4* __restrict__ p, int n4) {
    int i = blockIdx.x * blockDim.x + threadIdx.x;
    if (i < n4) p[i] = make_float4(0.f, 0.f, 0.f, 0.f);
}

// ---------------------------------------------------------------------------
// in-degree histogram
// ---------------------------------------------------------------------------
__global__ void degree_kernel(const int* __restrict__ dst, int* __restrict__ deg, int E) {
    int i = blockIdx.x * blockDim.x + threadIdx.x;
    if (i < E) atomicAdd(deg + __ldg(dst + i), 1);
}

// ---------------------------------------------------------------------------
// prefix scan (3 kernels): 1024 elems/block
// ---------------------------------------------------------------------------
__global__ __launch_bounds__(256) void scan1_kernel(const int* __restrict__ deg,
                                                    int* __restrict__ excl,
                                                    int* __restrict__ bsum, int n) {
    __shared__ int wsum[8];
    int t = threadIdx.x;
    int base = blockIdx.x * 1024 + t * 4;
    int v[4];
#pragma unroll
    for (int k = 0; k < 4; k++) v[k] = (base + k < n) ? deg[base + k] : 0;
    int tsum = v[0] + v[1] + v[2] + v[3];
    int lane = t & 31, w = t >> 5;
    int x = tsum;
#pragma unroll
    for (int o = 1; o < 32; o <<= 1) {
        int y = __shfl_up_sync(~0u, x, o);
        if (lane >= o) x += y;
    }
    if (lane == 31) wsum[w] = x;
    __syncthreads();
    if (t < 8) {
        int y = wsum[t];
#pragma unroll
        for (int o = 1; o < 8; o <<= 1) {
            int z = __shfl_up_sync(0xff, y, o);
            if (t >= o) y += z;
        }
        wsum[t] = y;
    }
    __syncthreads();
    int run = (w > 0 ? wsum[w - 1] : 0) + x - tsum;  // exclusive over threads
#pragma unroll
    for (int k = 0; k < 4; k++) {
        if (base + k < n) excl[base + k] = run;
        run += v[k];
    }
    if (t == 0) bsum[blockIdx.x] = wsum[7];
}

__global__ __launch_bounds__(512) void scan2_kernel(int* __restrict__ bsum, int nb) {
    __shared__ int wsum[16];
    int t = threadIdx.x;
    int v = (t < nb) ? bsum[t] : 0;
    int lane = t & 31, w = t >> 5;
    int x = v;
#pragma unroll
    for (int o = 1; o < 32; o <<= 1) {
        int y = __shfl_up_sync(~0u, x, o);
        if (lane >= o) x += y;
    }
    if (lane == 31) wsum[w] = x;
    __syncthreads();
    if (t < 16) {
        int y = wsum[t];
#pragma unroll
        for (int o = 1; o < 16; o <<= 1) {
            int z = __shfl_up_sync(0xffff, y, o);
            if (t >= o) y += z;
        }
        wsum[t] = y;
    }
    __syncthreads();
    int excl = (w > 0 ? wsum[w - 1] : 0) + x - v;
    if (t < nb) bsum[t] = excl;
}

__global__ void scan3_kernel(const int* __restrict__ excl, const int* __restrict__ bsum,
                             int* __restrict__ off, int* __restrict__ cur, int n, int E) {
    int i = blockIdx.x * blockDim.x + threadIdx.x;
    if (i < n) {
        int o = excl[i] + bsum[i >> 10];
        off[i] = o;
        cur[i] = o;
    }
    if (i == 0) off[n] = E;
}

// ---------------------------------------------------------------------------
// bucket permute: nbr sorted by dst
// ---------------------------------------------------------------------------
__global__ void bucket_kernel(const int* __restrict__ src, const int* __restrict__ dst,
                              int* __restrict__ cur, int* __restrict__ nbr, int E) {
    int i = blockIdx.x * blockDim.x + threadIdx.x;
    if (i < E) {
        int p = atomicAdd(cur + __ldg(dst + i), 1);
        nbr[p] = __ldg(src + i);
    }
}

// ---------------------------------------------------------------------------
// gather aggregation over fp16 features: mean over neighbors, 1 warp/node.
// lane owns 2 columns -> half2 (4B); one neighbor row = 128B = ONE L2 line.
// fp32 accumulation; mean stored as fp16.
// ---------------------------------------------------------------------------
__global__ __launch_bounds__(256) void agg_kernel(const __half* __restrict__ xh,
                                                  const int* __restrict__ off,
                                                  const int* __restrict__ nbr,
                                                  __half* __restrict__ mean, int N) {
    int warp = (blockIdx.x * blockDim.x + threadIdx.x) >> 5;
    if (warp >= N) return;
    int lane = threadIdx.x & 31;
    int s0 = __ldg(off + warp), s1 = __ldg(off + warp + 1);
    float ax = 0.f, ay = 0.f;
    const __half* xl = xh + lane * 2;
    int j = s0;
    for (; j + 32 <= s1; j += 32) {
        int myid = __ldg(nbr + j + lane);
#pragma unroll
        for (int k = 0; k < 32; k++) {
            int s = __shfl_sync(~0u, myid, k);
            __half2 h = *reinterpret_cast<const __half2*>(xl + (size_t)s * HD);
            float2 v = __half22float2(h);
            ax += v.x;
            ay += v.y;
        }
    }
    if (j < s1) {
        int cnt = s1 - j;
        int myid = (lane < cnt) ? __ldg(nbr + j + lane) : 0;
        for (int k = 0; k < cnt; k++) {
            int s = __shfl_sync(~0u, myid, k);
            __half2 h = *reinterpret_cast<const __half2*>(xl + (size_t)s * HD);
            float2 v = __half22float2(h);
            ax += v.x;
            ay += v.y;
        }
    }
    float inv = 1.0f / (float)max(s1 - s0, 1);
    __half2 o = __floats2half2_rn(ax * inv, ay * inv);
    *reinterpret_cast<__half2*>(mean + (size_t)warp * HD + lane * 2) = o;
}

// ---------------------------------------------------------------------------
// per-type encoder, register-tiled: 4 rows x 8 cols per thread.
// Writes fp32 output AND fp16 shadow directly.
// ---------------------------------------------------------------------------
template <int FIN>
__global__ __launch_bounds__(256) void encode_kernel(
    const float* __restrict__ x, const float* __restrict__ W,
    const float* __restrict__ b, float* __restrict__ out,
    __half* __restrict__ outh, int n) {
    __shared__ __align__(16) float sW[FIN * HD];
    __shared__ __align__(16) float sb[HD];
    for (int i = threadIdx.x; i < FIN * HD; i += 256) sW[i] = W[i];
    if (threadIdx.x < HD) sb[threadIdx.x] = b[threadIdx.x];
    __syncthreads();
    int cg = threadIdx.x & 7, rg = threadIdx.x >> 3;
    int row0 = blockIdx.x * 128 + rg * 4;
    int col0 = cg * 8;
    if (row0 >= n) return;

    ull acc[4][4];
    {
        const ull* sbp = reinterpret_cast<const ull*>(sb + col0);
#pragma unroll
        for (int i = 0; i < 4; i++)
#pragma unroll
            for (int c = 0; c < 4; c++) acc[i][c] = sbp[c];
    }
    int r[4];
#pragma unroll
    for (int i = 0; i < 4; i++) r[i] = min(row0 + i, n - 1);

#pragma unroll 1
    for (int kc = 0; kc < FIN / 4; kc++) {
        float4 xv[4];
#pragma unroll
        for (int i = 0; i < 4; i++)
            xv[i] = __ldg(reinterpret_cast<const float4*>(x + (size_t)r[i] * FIN + kc * 4));
#pragma unroll
        for (int kk = 0; kk < 4; kk++) {
            int k = kc * 4 + kk;
            const ulonglong2* pw =
                reinterpret_cast<const ulonglong2*>(sW + k * HD + col0);
            ulonglong2 w0 = pw[0], w1 = pw[1];
            float xk[4] = {0, 0, 0, 0};
#pragma unroll
            for (int i = 0; i < 4; i++)
                xk[i] = reinterpret_cast<const float*>(&xv[i])[kk];
#pragma unroll
            for (int i = 0; i < 4; i++) {
                ull xk2 = pack2(xk[i]);
                acc[i][0] = fma2(xk2, w0.x, acc[i][0]);
                acc[i][1] = fma2(xk2, w0.y, acc[i][1]);
                acc[i][2] = fma2(xk2, w1.x, acc[i][2]);
                acc[i][3] = fma2(xk2, w1.y, acc[i][3]);
            }
        }
    }
#pragma unroll
    for (int i = 0; i < 4; i++) {
        if (row0 + i < n) {
            float f[8];
            unpack2(acc[i][0], f[0], f[1]);
            unpack2(acc[i][1], f[2], f[3]);
            unpack2(acc[i][2], f[4], f[5]);
            unpack2(acc[i][3], f[6], f[7]);
            float4* o = reinterpret_cast<float4*>(out + (size_t)(row0 + i) * HD + col0);
            o[0] = make_float4(f[0], f[1], f[2], f[3]);
            o[1] = make_float4(f[4], f[5], f[6], f[7]);
            uint4 hp;
            pack_half8(f, hp);
            *reinterpret_cast<uint4*>(outh + (size_t)(row0 + i) * HD + col0) = hp;
        }
    }
}

// ---------------------------------------------------------------------------
// SAGE combine, register-tiled: out = relu( mean @ Wl + x @ Wr + b ).
// mean read as fp16. Optionally writes fp16 shadow (outh != nullptr).
// ---------------------------------------------------------------------------
__global__ __launch_bounds__(256) void sage_combine_kernel(
    const float* __restrict__ x, const __half* __restrict__ mean,
    const float* __restrict__ Wl, const float* __restrict__ Wr,
    const float* __restrict__ b, float* __restrict__ out,
    __half* __restrict__ outh, int n) {
    __shared__ __align__(16) float sWl[HD * HD];
    __shared__ __align__(16) float sWr[HD * HD];
    __shared__ __align__(16) float sb[HD];
    for (int i = threadIdx.x; i < HD * HD; i += 256) {
        sWl[i] = Wl[i];
        sWr[i] = Wr[i];
    }
    if (threadIdx.x < HD) sb[threadIdx.x] = b[threadIdx.x];
    __syncthreads();
    int cg = threadIdx.x & 7, rg = threadIdx.x >> 3;
    int row0 = blockIdx.x * 128 + rg * 4;
    int col0 = cg * 8;
    if (row0 >= n) return;

    ull acc[4][4];
    {
        const ull* sbp = reinterpret_cast<const ull*>(sb + col0);
#pragma unroll
        for (int i = 0; i < 4; i++)
#pragma unroll
            for (int c = 0; c < 4; c++) acc[i][c] = sbp[c];
    }
    int r[4];
#pragma unroll
    for (int i = 0; i < 4; i++) r[i] = min(row0 + i, n - 1);

#pragma unroll 1
    for (int kc = 0; kc < 16; kc++) {
        float4 xv[4], mv[4];
#pragma unroll
        for (int i = 0; i < 4; i++) {
            xv[i] = __ldg(reinterpret_cast<const float4*>(x + (size_t)r[i] * HD + kc * 4));
            mv[i] = load_half4(mean + (size_t)r[i] * HD + kc * 4);
        }
#pragma unroll
        for (int kk = 0; kk < 4; kk++) {
            int k = kc * 4 + kk;
            const ulonglong2* pl =
                reinterpret_cast<const ulonglong2*>(sWl + k * HD + col0);
            const ulonglong2* pr =
                reinterpret_cast<const ulonglong2*>(sWr + k * HD + col0);
            ulonglong2 l0 = pl[0], l1 = pl[1];
            ulonglong2 r0 = pr[0], r1 = pr[1];
#pragma unroll
            for (int i = 0; i < 4; i++) {
                ull mk2 = pack2(reinterpret_cast<const float*>(&mv[i])[kk]);
                ull xk2 = pack2(reinterpret_cast<const float*>(&xv[i])[kk]);
                acc[i][0] = fma2(mk2, l0.x, acc[i][0]);
                acc[i][0] = fma2(xk2, r0.x, acc[i][0]);
                acc[i][1] = fma2(mk2, l0.y, acc[i][1]);
                acc[i][1] = fma2(xk2, r0.y, acc[i][1]);
                acc[i][2] = fma2(mk2, l1.x, acc[i][2]);
                acc[i][2] = fma2(xk2, r1.x, acc[i][2]);
                acc[i][3] = fma2(mk2, l1.y, acc[i][3]);
                acc[i][3] = fma2(xk2, r1.y, acc[i][3]);
            }
        }
    }
#pragma unroll
    for (int i = 0; i < 4; i++) {
        if (row0 + i < n) {
            float f[8];
            unpack2(acc[i][0], f[0], f[1]);
            unpack2(acc[i][1], f[2], f[3]);
            unpack2(acc[i][2], f[4], f[5]);
            unpack2(acc[i][3], f[6], f[7]);
#pragma unroll
            for (int c = 0; c < 8; c++) f[c] = fmaxf(f[c], 0.f);
            float4* o = reinterpret_cast<float4*>(out + (size_t)(row0 + i) * HD + col0);
            o[0] = make_float4(f[0], f[1], f[2], f[3]);
            o[1] = make_float4(f[4], f[5], f[6], f[7]);
            if (outh) {
                uint4 hp;
                pack_half8(f, hp);
                *reinterpret_cast<uint4*>(outh + (size_t)(row0 + i) * HD + col0) = hp;
            }
        }
    }
}

// ---------------------------------------------------------------------------
// classifier, register-tiled phase 1 (4 rows x 8 hidden cols per thread),
// hidden staged in SMEM (stride 33 -> conflict-free), thread-per-row phase 2
// ---------------------------------------------------------------------------
#define CLS_STRIDE 33
__global__ __launch_bounds__(256) void classify_kernel(
    const float* __restrict__ x,
    const float* __restrict__ Wc1, const float* __restrict__ bc1,
    const float* __restrict__ Wc2, const float* __restrict__ bc2,
    float* __restrict__ out, int n) {
    __shared__ __align__(16) float sW1[HD * 32];
    __shared__ __align__(16) float sW2[32 * 2];
    __shared__ __align__(16) float sb1[32];
    __shared__ float sb2[2];
    __shared__ float sh[256 * CLS_STRIDE];
    for (int i = threadIdx.x; i < HD * 32; i += 256) sW1[i] = Wc1[i];
    if (threadIdx.x < 64) sW2[threadIdx.x] = Wc2[threadIdx.x];
    if (threadIdx.x < 32) sb1[threadIdx.x] = bc1[threadIdx.x];
    if (threadIdx.x < 2) sb2[threadIdx.x] = bc2[threadIdx.x];
    __syncthreads();

    int cg = threadIdx.x & 3, rg = threadIdx.x >> 2;  // 4 colgroups x 64 rowgroups
    int row0 = blockIdx.x * 256 + rg * 4;
    int col0 = cg * 8;

    if (row0 < n) {
        ull acc[4][4];
        {
            const ull* sbp = reinterpret_cast<const ull*>(sb1 + col0);
#pragma unroll
            for (int i = 0; i < 4; i++)
#pragma unroll
                for (int c = 0; c < 4; c++) acc[i][c] = sbp[c];
        }
        int r[4];
#pragma unroll
        for (int i = 0; i < 4; i++) r[i] = min(row0 + i, n - 1);

#pragma unroll 1
        for (int kc = 0; kc < 16; kc++) {
            float4 xv[4];
#pragma unroll
            for (int i = 0; i < 4; i++)
                xv[i] = __ldg(reinterpret_cast<const float4*>(x + (size_t)r[i] * HD + kc * 4));
#pragma unroll
            for (int kk = 0; kk < 4; kk++) {
                int k = kc * 4 + kk;
                const ulonglong2* pw =
                    reinterpret_cast<const ulonglong2*>(sW1 + k * 32 + col0);
                ulonglong2 w0 = pw[0], w1 = pw[1];
#pragma unroll
                for (int i = 0; i < 4; i++) {
                    ull xk2 = pack2(reinterpret_cast<const float*>(&xv[i])[kk]);
                    acc[i][0] = fma2(xk2, w0.x, acc[i][0]);
                    acc[i][1] = fma2(xk2, w0.y, acc[i][1]);
                    acc[i][2] = fma2(xk2, w1.x, acc[i][2]);
                    acc[i][3] = fma2(xk2, w1.y, acc[i][3]);
                }
            }
        }
        // relu + stage hidden to SMEM
#pragma unroll
        for (int i = 0; i < 4; i++) {
            float h[8];
            unpack2(acc[i][0], h[0], h[1]);
            unpack2(acc[i][1], h[2], h[3]);
            unpack2(acc[i][2], h[4], h[5]);
            unpack2(acc[i][3], h[6], h[7]);
            float* dstp = sh + (rg * 4 + i) * CLS_STRIDE + col0;
#pragma unroll
            for (int c = 0; c < 8; c++) dstp[c] = fmaxf(h[c], 0.f);
        }
    }
    __syncthreads();

    // phase 2: thread-per-row 32 -> 2
    int row = blockIdx.x * 256 + threadIdx.x;
    if (row >= n) return;
    const float* hr = sh + threadIdx.x * CLS_STRIDE;
    float o0 = sb2[0], o1 = sb2[1];
#pragma unroll
    for (int j = 0; j < 32; j++) {
        float hv = hr[j];
        o0 += hv * sW2[j * 2 + 0];
        o1 += hv * sW2[j * 2 + 1];
    }
    out[(size_t)row * 2 + 0] = o0;
    out[(size_t)row * 2 + 1] = o1;
}

// ---------------------------------------------------------------------------
// launch (forked capture: encoders on side stream ∥ CSR build on main)
// ---------------------------------------------------------------------------
extern "C" void kernel_launch(void* const* d_in, const int* in_sizes, int n_in,
                              void* d_out, int out_size) {
    const float* x_ind = (const float*)d_in[0];
    const float* x_com = (const float*)d_in[1];
    const float* x_tru = (const float*)d_in[2];
    const int*   ei    = (const int*)d_in[3];
    const float* W_ind = (const float*)d_in[4];
    const float* b_ind = (const float*)d_in[5];
    const float* W_com = (const float*)d_in[6];
    const float* b_com = (const float*)d_in[7];
    const float* W_tru = (const float*)d_in[8];
    const float* b_tru = (const float*)d_in[9];
    const float* W1l = (const float*)d_in[10];
    const float* W1r = (const float*)d_in[11];
    const float* b1  = (const float*)d_in[12];
    const float* W2l = (const float*)d_in[13];
    const float* W2r = (const float*)d_in[14];
    const float* b2  = (const float*)d_in[15];
    const float* Wc1 = (const float*)d_in[16];
    const float* bc1 = (const float*)d_in[17];
    const float* Wc2 = (const float*)d_in[18];
    const float* bc2 = (const float*)d_in[19];

    int n_ind = in_sizes[0] / 32;
    int n_com = in_sizes[1] / 48;
    int n_tru = in_sizes[2] / 24;
    int N = n_ind + n_com + n_tru;
    int E = in_sizes[3] / 2;
    const int* src = ei;
    const int* dst = ei + E;

    float *gx, *gy;
    __half *gxh, *gaggh;
    int *gdeg, *gexcl, *goff, *gcur, *gbsum, *gnbr;
    cudaGetSymbolAddress((void**)&gx, g_x);
    cudaGetSymbolAddress((void**)&gy, g_y);
    cudaGetSymbolAddress((void**)&gxh, g_xh);
    cudaGetSymbolAddress((void**)&gaggh, g_aggh);
    cudaGetSymbolAddress((void**)&gdeg, g_deg);
    cudaGetSymbolAddress((void**)&gexcl, g_excl);
    cudaGetSymbolAddress((void**)&goff, g_off);
    cudaGetSymbolAddress((void**)&gcur, g_cur);
    cudaGetSymbolAddress((void**)&gbsum, g_bsum);
    cudaGetSymbolAddress((void**)&gnbr, g_nbr);

    // one-time stream/event setup (first call is the uncaptured correctness run)
    static cudaStream_t s2 = nullptr;
    static cudaEvent_t evFork = nullptr, evEnc = nullptr;
    if (s2 == nullptr) {
        cudaStreamCreateWithFlags(&s2, cudaStreamNonBlocking);
        cudaEventCreateWithFlags(&evFork, cudaEventDisableTiming);
        cudaEventCreateWithFlags(&evEnc, cudaEventDisableTiming);
    }

    // ---- fork: side stream joins the capture graph
    cudaEventRecord(evFork, 0);
    cudaStreamWaitEvent(s2, evFork, 0);

    // ---- main stream: CSR build
    int nInt4 = (N + 3) / 4;
    zero_kernel<<<(nInt4 + 255) / 256, 256>>>((float4*)gdeg, nInt4);
    degree_kernel<<<(E + 255) / 256, 256>>>(dst, gdeg, E);
    int nb = (N + 1023) / 1024;
    scan1_kernel<<<nb, 256>>>(gdeg, gexcl, gbsum, N);

    // ---- side stream: encoders (write fp32 + fp16 shadow directly)
    encode_kernel<48><<<(n_com + 127) / 128, 256, 0, s2>>>(
        x_com, W_com, b_com, gx + (size_t)n_ind * HD, gxh + (size_t)n_ind * HD, n_com);
    encode_kernel<32><<<(n_ind + 127) / 128, 256, 0, s2>>>(
        x_ind, W_ind, b_ind, gx, gxh, n_ind);
    encode_kernel<24><<<(n_tru + 127) / 128, 256, 0, s2>>>(
        x_tru, W_tru, b_tru, gx + (size_t)(n_ind + n_com) * HD,
        gxh + (size_t)(n_ind + n_com) * HD, n_tru);
    cudaEventRecord(evEnc, s2);

    // ---- main stream: rest of CSR build
    scan2_kernel<<<1, 512>>>(gbsum, nb);
    scan3_kernel<<<(N + 255) / 256, 256>>>(gexcl, gbsum, goff, gcur, N, E);
    bucket_kernel<<<(E + 255) / 256, 256>>>(src, dst, gcur, gnbr, E);

    // ---- join: layers need both encoders and CSR
    cudaStreamWaitEvent(0, evEnc, 0);

    // ---- SAGE layer 1: gather fp16 -> fp16 mean; combine -> g_y (+ shadow)
    agg_kernel<<<(N * 32 + 255) / 256, 256>>>(gxh, goff, gnbr, gaggh, N);
    sage_combine_kernel<<<(N + 127) / 128, 256>>>(gx, gaggh, W1l, W1r, b1, gy, gxh, N);

    // ---- SAGE layer 2
    agg_kernel<<<(N * 32 + 255) / 256, 256>>>(gxh, goff, gnbr, gaggh, N);
    sage_combine_kernel<<<(N + 127) / 128, 256>>>(gy, gaggh, W2l, W2r, b2, gx, nullptr, N);

    // ---- classifier -> d_out
    classify_kernel<<<(N + 255) / 256, 256>>>(gx, Wc1, bc1, Wc2, bc2, (float*)d_out, N);
}

// round 16
// speedup vs baseline: 1.0649x; 1.0263x over previous
#include <cuda_runtime.h>
#include <cuda_fp16.h>
#include <cstdint>

#define HD 64
#define NMAX 300000
#define EMAX 4800000

typedef unsigned long long ull;

// Scratch — device globals (no cudaMalloc allowed).
__device__ float  g_x[(size_t)NMAX * HD];    // combine2 output (fp32, classifier input)
__device__ __half g_xh[(size_t)NMAX * HD];   // encoded features (fp16)
__device__ __half g_yh[(size_t)NMAX * HD];   // layer-1 output (fp16)
__device__ __half g_aggh[(size_t)NMAX * HD]; // neighbor-mean buffer (fp16)
__device__ int    g_deg[NMAX];               // in-degree
__device__ int    g_excl[NMAX];              // block-local exclusive scan
__device__ int    g_off[NMAX + 1];           // CSR offsets
__device__ int    g_cur[NMAX];               // bucket cursors
__device__ int    g_bsum[512];               // per-block sums for scan
__device__ int    g_nbr[EMAX];               // CSR neighbor (src) ids

// ---------------------------------------------------------------------------
// packed f32x2 helpers (sm_103a FFMA2 — only reachable via PTX)
// ---------------------------------------------------------------------------
__device__ __forceinline__ ull fma2(ull a, ull b, ull c) {
    ull d;
    asm("fma.rn.f32x2 %0, %1, %2, %3;" : "=l"(d) : "l"(a), "l"(b), "l"(c));
    return d;
}
__device__ __forceinline__ ull pack2(float x) {
    ull d;
    asm("mov.b64 %0, {%1, %1};" : "=l"(d) : "f"(x));
    return d;
}
__device__ __forceinline__ void unpack2(ull v, float& lo, float& hi) {
    asm("mov.b64 {%0, %1}, %2;" : "=f"(lo), "=f"(hi) : "l"(v));
}
// pack 8 floats -> 8 fp16 in one 16B store payload
__device__ __forceinline__ void pack_half8(const float* f, uint4& out) {
    __half2 h0 = __floats2half2_rn(f[0], f[1]);
    __half2 h1 = __floats2half2_rn(f[2], f[3]);
    __half2 h2 = __floats2half2_rn(f[4], f[5]);
    __half2 h3 = __floats2half2_rn(f[6], f[7]);
    out.x = *reinterpret_cast<unsigned*>(&h0);
    out.y = *reinterpret_cast<unsigned*>(&h1);
    out.z = *reinterpret_cast<unsigned*>(&h2);
    out.w = *reinterpret_cast<unsigned*>(&h3);
}
// load 4 fp16 (8B) -> float4
__device__ __forceinline__ float4 load_half4(const __half* p) {
    uint2 raw = __ldg(reinterpret_cast<const uint2*>(p));
    __half2 h0 = *reinterpret_cast<__half2*>(&raw.x);
    __half2 h1 = *reinterpret_cast<__half2*>(&raw.y);
    float2 a = __half22float2(h0);
    float2 c = __half22float2(h1);
    return make_float4(a.x, a.y, c.x, c.y);
}

// ---------------------------------------------------------------------------
// zero fill (16B granularity)
// ---------------------------------------------------------------------------
__global__ void zero_kernel(float4* __restrict__ p, int n4) {
    int i = blockIdx.x * blockDim.x + threadIdx.x;
    if (i < n4) p[i] = make_float4(0.f, 0.f, 0.f, 0.f);
}

// ---------------------------------------------------------------------------
// in-degree histogram
// ---------------------------------------------------------------------------
__global__ void degree_kernel(const int* __restrict__ dst, int* __restrict__ deg, int E) {
    int i = blockIdx.x * blockDim.x + threadIdx.x;
    if (i < E) atomicAdd(deg + __ldg(dst + i), 1);
}

// ---------------------------------------------------------------------------
// prefix scan (3 kernels): 1024 elems/block
// ---------------------------------------------------------------------------
__global__ __launch_bounds__(256) void scan1_kernel(const int* __restrict__ deg,
                                                    int* __restrict__ excl,
                                                    int* __restrict__ bsum, int n) {
    __shared__ int wsum[8];
    int t = threadIdx.x;
    int base = blockIdx.x * 1024 + t * 4;
    int v[4];
#pragma unroll
    for (int k = 0; k < 4; k++) v[k] = (base + k < n) ? deg[base + k] : 0;
    int tsum = v[0] + v[1] + v[2] + v[3];
    int lane = t & 31, w = t >> 5;
    int x = tsum;
#pragma unroll
    for (int o = 1; o < 32; o <<= 1) {
        int y = __shfl_up_sync(~0u, x, o);
        if (lane >= o) x += y;
    }
    if (lane == 31) wsum[w] = x;
    __syncthreads();
    if (t < 8) {
        int y = wsum[t];
#pragma unroll
        for (int o = 1; o < 8; o <<= 1) {
            int z = __shfl_up_sync(0xff, y, o);
            if (t >= o) y += z;
        }
        wsum[t] = y;
    }
    __syncthreads();
    int run = (w > 0 ? wsum[w - 1] : 0) + x - tsum;  // exclusive over threads
#pragma unroll
    for (int k = 0; k < 4; k++) {
        if (base + k < n) excl[base + k] = run;
        run += v[k];
    }
    if (t == 0) bsum[blockIdx.x] = wsum[7];
}

__global__ __launch_bounds__(512) void scan2_kernel(int* __restrict__ bsum, int nb) {
    __shared__ int wsum[16];
    int t = threadIdx.x;
    int v = (t < nb) ? bsum[t] : 0;
    int lane = t & 31, w = t >> 5;
    int x = v;
#pragma unroll
    for (int o = 1; o < 32; o <<= 1) {
        int y = __shfl_up_sync(~0u, x, o);
        if (lane >= o) x += y;
    }
    if (lane == 31) wsum[w] = x;
    __syncthreads();
    if (t < 16) {
        int y = wsum[t];
#pragma unroll
        for (int o = 1; o < 16; o <<= 1) {
            int z = __shfl_up_sync(0xffff, y, o);
            if (t >= o) y += z;
        }
        wsum[t] = y;
    }
    __syncthreads();
    int excl = (w > 0 ? wsum[w - 1] : 0) + x - v;
    if (t < nb) bsum[t] = excl;
}

__global__ void scan3_kernel(const int* __restrict__ excl, const int* __restrict__ bsum,
                             int* __restrict__ off, int* __restrict__ cur, int n, int E) {
    int i = blockIdx.x * blockDim.x + threadIdx.x;
    if (i < n) {
        int o = excl[i] + bsum[i >> 10];
        off[i] = o;
        cur[i] = o;
    }
    if (i == 0) off[n] = E;
}

// ---------------------------------------------------------------------------
// bucket permute: nbr sorted by dst
// ---------------------------------------------------------------------------
__global__ void bucket_kernel(const int* __restrict__ src, const int* __restrict__ dst,
                              int* __restrict__ cur, int* __restrict__ nbr, int E) {
    int i = blockIdx.x * blockDim.x + threadIdx.x;
    if (i < E) {
        int p = atomicAdd(cur + __ldg(dst + i), 1);
        nbr[p] = __ldg(src + i);
    }
}

// ---------------------------------------------------------------------------
// gather aggregation over fp16 features: mean over neighbors, 1 warp/node.
// lane owns 2 columns -> half2 (4B); one neighbor row = 128B = ONE L2 line.
// fp32 accumulation; mean stored as fp16.
// ---------------------------------------------------------------------------
__global__ __launch_bounds__(256) void agg_kernel(const __half* __restrict__ xh,
                                                  const int* __restrict__ off,
                                                  const int* __restrict__ nbr,
                                                  __half* __restrict__ mean, int N) {
    int warp = (blockIdx.x * blockDim.x + threadIdx.x) >> 5;
    if (warp >= N) return;
    int lane = threadIdx.x & 31;
    int s0 = __ldg(off + warp), s1 = __ldg(off + warp + 1);
    float ax = 0.f, ay = 0.f;
    const __half* xl = xh + lane * 2;
    int j = s0;
    for (; j + 32 <= s1; j += 32) {
        int myid = __ldg(nbr + j + lane);
#pragma unroll
        for (int k = 0; k < 32; k++) {
            int s = __shfl_sync(~0u, myid, k);
            __half2 h = *reinterpret_cast<const __half2*>(xl + (size_t)s * HD);
            float2 v = __half22float2(h);
            ax += v.x;
            ay += v.y;
        }
    }
    if (j < s1) {
        int cnt = s1 - j;
        int myid = (lane < cnt) ? __ldg(nbr + j + lane) : 0;
        for (int k = 0; k < cnt; k++) {
            int s = __shfl_sync(~0u, myid, k);
            __half2 h = *reinterpret_cast<const __half2*>(xl + (size_t)s * HD);
            float2 v = __half22float2(h);
            ax += v.x;
            ay += v.y;
        }
    }
    float inv = 1.0f / (float)max(s1 - s0, 1);
    __half2 o = __floats2half2_rn(ax * inv, ay * inv);
    *reinterpret_cast<__half2*>(mean + (size_t)warp * HD + lane * 2) = o;
}

// ---------------------------------------------------------------------------
// per-type encoder, register-tiled: 4 rows x 8 cols per thread.
// Writes fp16 features ONLY (the whole layer pipeline runs on fp16 features).
// ---------------------------------------------------------------------------
template <int FIN>
__global__ __launch_bounds__(256) void encode_kernel(
    const float* __restrict__ x, const float* __restrict__ W,
    const float* __restrict__ b, __half* __restrict__ outh, int n) {
    __shared__ __align__(16) float sW[FIN * HD];
    __shared__ __align__(16) float sb[HD];
    for (int i = threadIdx.x; i < FIN * HD; i += 256) sW[i] = W[i];
    if (threadIdx.x < HD) sb[threadIdx.x] = b[threadIdx.x];
    __syncthreads();
    int cg = threadIdx.x & 7, rg = threadIdx.x >> 3;
    int row0 = blockIdx.x * 128 + rg * 4;
    int col0 = cg * 8;
    if (row0 >= n) return;

    ull acc[4][4];
    {
        const ull* sbp = reinterpret_cast<const ull*>(sb + col0);
#pragma unroll
        for (int i = 0; i < 4; i++)
#pragma unroll
            for (int c = 0; c < 4; c++) acc[i][c] = sbp[c];
    }
    int r[4];
#pragma unroll
    for (int i = 0; i < 4; i++) r[i] = min(row0 + i, n - 1);

#pragma unroll 1
    for (int kc = 0; kc < FIN / 4; kc++) {
        float4 xv[4];
#pragma unroll
        for (int i = 0; i < 4; i++)
            xv[i] = __ldg(reinterpret_cast<const float4*>(x + (size_t)r[i] * FIN + kc * 4));
#pragma unroll
        for (int kk = 0; kk < 4; kk++) {
            int k = kc * 4 + kk;
            const ulonglong2* pw =
                reinterpret_cast<const ulonglong2*>(sW + k * HD + col0);
            ulonglong2 w0 = pw[0], w1 = pw[1];
            float xk[4] = {0, 0, 0, 0};
#pragma unroll
            for (int i = 0; i < 4; i++)
                xk[i] = reinterpret_cast<const float*>(&xv[i])[kk];
#pragma unroll
            for (int i = 0; i < 4; i++) {
                ull xk2 = pack2(xk[i]);
                acc[i][0] = fma2(xk2, w0.x, acc[i][0]);
                acc[i][1] = fma2(xk2, w0.y, acc[i][1]);
                acc[i][2] = fma2(xk2, w1.x, acc[i][2]);
                acc[i][3] = fma2(xk2, w1.y, acc[i][3]);
            }
        }
    }
#pragma unroll
    for (int i = 0; i < 4; i++) {
        if (row0 + i < n) {
            float f[8];
            unpack2(acc[i][0], f[0], f[1]);
            unpack2(acc[i][1], f[2], f[3]);
            unpack2(acc[i][2], f[4], f[5]);
            unpack2(acc[i][3], f[6], f[7]);
            uint4 hp;
            pack_half8(f, hp);
            *reinterpret_cast<uint4*>(outh + (size_t)(row0 + i) * HD + col0) = hp;
        }
    }
}

// ---------------------------------------------------------------------------
// SAGE combine, register-tiled: out = relu( mean @ Wl + x @ Wr + b ).
// x and mean both fp16. Writes fp16 (outh) and/or fp32 (outf).
// ---------------------------------------------------------------------------
__global__ __launch_bounds__(256) void sage_combine_kernel(
    const __half* __restrict__ x, const __half* __restrict__ mean,
    const float* __restrict__ Wl, const float* __restrict__ Wr,
    const float* __restrict__ b, float* __restrict__ outf,
    __half* __restrict__ outh, int n) {
    __shared__ __align__(16) float sWl[HD * HD];
    __shared__ __align__(16) float sWr[HD * HD];
    __shared__ __align__(16) float sb[HD];
    for (int i = threadIdx.x; i < HD * HD; i += 256) {
        sWl[i] = Wl[i];
        sWr[i] = Wr[i];
    }
    if (threadIdx.x < HD) sb[threadIdx.x] = b[threadIdx.x];
    __syncthreads();
    int cg = threadIdx.x & 7, rg = threadIdx.x >> 3;
    int row0 = blockIdx.x * 128 + rg * 4;
    int col0 = cg * 8;
    if (row0 >= n) return;

    ull acc[4][4];
    {
        const ull* sbp = reinterpret_cast<const ull*>(sb + col0);
#pragma unroll
        for (int i = 0; i < 4; i++)
#pragma unroll
            for (int c = 0; c < 4; c++) acc[i][c] = sbp[c];
    }
    int r[4];
#pragma unroll
    for (int i = 0; i < 4; i++) r[i] = min(row0 + i, n - 1);

#pragma unroll 1
    for (int kc = 0; kc < 16; kc++) {
        float4 xv[4], mv[4];
#pragma unroll
        for (int i = 0; i < 4; i++) {
            xv[i] = load_half4(x + (size_t)r[i] * HD + kc * 4);
            mv[i] = load_half4(mean + (size_t)r[i] * HD + kc * 4);
        }
#pragma unroll
        for (int kk = 0; kk < 4; kk++) {
            int k = kc * 4 + kk;
            const ulonglong2* pl =
                reinterpret_cast<const ulonglong2*>(sWl + k * HD + col0);
            const ulonglong2* pr =
                reinterpret_cast<const ulonglong2*>(sWr + k * HD + col0);
            ulonglong2 l0 = pl[0], l1 = pl[1];
            ulonglong2 r0 = pr[0], r1 = pr[1];
#pragma unroll
            for (int i = 0; i < 4; i++) {
                ull mk2 = pack2(reinterpret_cast<const float*>(&mv[i])[kk]);
                ull xk2 = pack2(reinterpret_cast<const float*>(&xv[i])[kk]);
                acc[i][0] = fma2(mk2, l0.x, acc[i][0]);
                acc[i][0] = fma2(xk2, r0.x, acc[i][0]);
                acc[i][1] = fma2(mk2, l0.y, acc[i][1]);
                acc[i][1] = fma2(xk2, r0.y, acc[i][1]);
                acc[i][2] = fma2(mk2, l1.x, acc[i][2]);
                acc[i][2] = fma2(xk2, r1.x, acc[i][2]);
                acc[i][3] = fma2(mk2, l1.y, acc[i][3]);
                acc[i][3] = fma2(xk2, r1.y, acc[i][3]);
            }
        }
    }
#pragma unroll
    for (int i = 0; i < 4; i++) {
        if (row0 + i < n) {
            float f[8];
            unpack2(acc[i][0], f[0], f[1]);
            unpack2(acc[i][1], f[2], f[3]);
            unpack2(acc[i][2], f[4], f[5]);
            unpack2(acc[i][3], f[6], f[7]);
#pragma unroll
            for (int c = 0; c < 8; c++) f[c] = fmaxf(f[c], 0.f);
            if (outf) {
                float4* o = reinterpret_cast<float4*>(outf + (size_t)(row0 + i) * HD + col0);
                o[0] = make_float4(f[0], f[1], f[2], f[3]);
                o[1] = make_float4(f[4], f[5], f[6], f[7]);
            }
            if (outh) {
                uint4 hp;
                pack_half8(f, hp);
                *reinterpret_cast<uint4*>(outh + (size_t)(row0 + i) * HD + col0) = hp;
            }
        }
    }
}

// ---------------------------------------------------------------------------
// classifier, register-tiled phase 1 (4 rows x 8 hidden cols per thread),
// hidden staged in SMEM (stride 33 -> conflict-free), thread-per-row phase 2
// ---------------------------------------------------------------------------
#define CLS_STRIDE 33
__global__ __launch_bounds__(256) void classify_kernel(
    const float* __restrict__ x,
    const float* __restrict__ Wc1, const float* __restrict__ bc1,
    const float* __restrict__ Wc2, const float* __restrict__ bc2,
    float* __restrict__ out, int n) {
    __shared__ __align__(16) float sW1[HD * 32];
    __shared__ __align__(16) float sW2[32 * 2];
    __shared__ __align__(16) float sb1[32];
    __shared__ float sb2[2];
    __shared__ float sh[256 * CLS_STRIDE];
    for (int i = threadIdx.x; i < HD * 32; i += 256) sW1[i] = Wc1[i];
    if (threadIdx.x < 64) sW2[threadIdx.x] = Wc2[threadIdx.x];
    if (threadIdx.x < 32) sb1[threadIdx.x] = bc1[threadIdx.x];
    if (threadIdx.x < 2) sb2[threadIdx.x] = bc2[threadIdx.x];
    __syncthreads();

    int cg = threadIdx.x & 3, rg = threadIdx.x >> 2;  // 4 colgroups x 64 rowgroups
    int row0 = blockIdx.x * 256 + rg * 4;
    int col0 = cg * 8;

    if (row0 < n) {
        ull acc[4][4];
        {
            const ull* sbp = reinterpret_cast<const ull*>(sb1 + col0);
#pragma unroll
            for (int i = 0; i < 4; i++)
#pragma unroll
                for (int c = 0; c < 4; c++) acc[i][c] = sbp[c];
        }
        int r[4];
#pragma unroll
        for (int i = 0; i < 4; i++) r[i] = min(row0 + i, n - 1);

#pragma unroll 1
        for (int kc = 0; kc < 16; kc++) {
            float4 xv[4];
#pragma unroll
            for (int i = 0; i < 4; i++)
                xv[i] = __ldg(reinterpret_cast<const float4*>(x + (size_t)r[i] * HD + kc * 4));
#pragma unroll
            for (int kk = 0; kk < 4; kk++) {
                int k = kc * 4 + kk;
                const ulonglong2* pw =
                    reinterpret_cast<const ulonglong2*>(sW1 + k * 32 + col0);
                ulonglong2 w0 = pw[0], w1 = pw[1];
#pragma unroll
                for (int i = 0; i < 4; i++) {
                    ull xk2 = pack2(reinterpret_cast<const float*>(&xv[i])[kk]);
                    acc[i][0] = fma2(xk2, w0.x, acc[i][0]);
                    acc[i][1] = fma2(xk2, w0.y, acc[i][1]);
                    acc[i][2] = fma2(xk2, w1.x, acc[i][2]);
                    acc[i][3] = fma2(xk2, w1.y, acc[i][3]);
                }
            }
        }
        // relu + stage hidden to SMEM
#pragma unroll
        for (int i = 0; i < 4; i++) {
            float h[8];
            unpack2(acc[i][0], h[0], h[1]);
            unpack2(acc[i][1], h[2], h[3]);
            unpack2(acc[i][2], h[4], h[5]);
            unpack2(acc[i][3], h[6], h[7]);
            float* dstp = sh + (rg * 4 + i) * CLS_STRIDE + col0;
#pragma unroll
            for (int c = 0; c < 8; c++) dstp[c] = fmaxf(h[c], 0.f);
        }
    }
    __syncthreads();

    // phase 2: thread-per-row 32 -> 2
    int row = blockIdx.x * 256 + threadIdx.x;
    if (row >= n) return;
    const float* hr = sh + threadIdx.x * CLS_STRIDE;
    float o0 = sb2[0], o1 = sb2[1];
#pragma unroll
    for (int j = 0; j < 32; j++) {
        float hv = hr[j];
        o0 += hv * sW2[j * 2 + 0];
        o1 += hv * sW2[j * 2 + 1];
    }
    out[(size_t)row * 2 + 0] = o0;
    out[(size_t)row * 2 + 1] = o1;
}

// ---------------------------------------------------------------------------
// launch (forked capture: encoders on side stream ∥ CSR build on main)
// ---------------------------------------------------------------------------
extern "C" void kernel_launch(void* const* d_in, const int* in_sizes, int n_in,
                              void* d_out, int out_size) {
    const float* x_ind = (const float*)d_in[0];
    const float* x_com = (const float*)d_in[1];
    const float* x_tru = (const float*)d_in[2];
    const int*   ei    = (const int*)d_in[3];
    const float* W_ind = (const float*)d_in[4];
    const float* b_ind = (const float*)d_in[5];
    const float* W_com = (const float*)d_in[6];
    const float* b_com = (const float*)d_in[7];
    const float* W_tru = (const float*)d_in[8];
    const float* b_tru = (const float*)d_in[9];
    const float* W1l = (const float*)d_in[10];
    const float* W1r = (const float*)d_in[11];
    const float* b1  = (const float*)d_in[12];
    const float* W2l = (const float*)d_in[13];
    const float* W2r = (const float*)d_in[14];
    const float* b2  = (const float*)d_in[15];
    const float* Wc1 = (const float*)d_in[16];
    const float* bc1 = (const float*)d_in[17];
    const float* Wc2 = (const float*)d_in[18];
    const float* bc2 = (const float*)d_in[19];

    int n_ind = in_sizes[0] / 32;
    int n_com = in_sizes[1] / 48;
    int n_tru = in_sizes[2] / 24;
    int N = n_ind + n_com + n_tru;
    int E = in_sizes[3] / 2;
    const int* src = ei;
    const int* dst = ei + E;

    float* gx;
    __half *gxh, *gyh, *gaggh;
    int *gdeg, *gexcl, *goff, *gcur, *gbsum, *gnbr;
    cudaGetSymbolAddress((void**)&gx, g_x);
    cudaGetSymbolAddress((void**)&gxh, g_xh);
    cudaGetSymbolAddress((void**)&gyh, g_yh);
    cudaGetSymbolAddress((void**)&gaggh, g_aggh);
    cudaGetSymbolAddress((void**)&gdeg, g_deg);
    cudaGetSymbolAddress((void**)&gexcl, g_excl);
    cudaGetSymbolAddress((void**)&goff, g_off);
    cudaGetSymbolAddress((void**)&gcur, g_cur);
    cudaGetSymbolAddress((void**)&gbsum, g_bsum);
    cudaGetSymbolAddress((void**)&gnbr, g_nbr);

    // one-time stream/event setup (first call is the uncaptured correctness run)
    static cudaStream_t s2 = nullptr;
    static cudaEvent_t evFork = nullptr, evEnc = nullptr;
    if (s2 == nullptr) {
        cudaStreamCreateWithFlags(&s2, cudaStreamNonBlocking);
        cudaEventCreateWithFlags(&evFork, cudaEventDisableTiming);
        cudaEventCreateWithFlags(&evEnc, cudaEventDisableTiming);
    }

    // ---- fork: side stream joins the capture graph
    cudaEventRecord(evFork, 0);
    cudaStreamWaitEvent(s2, evFork, 0);

    // ---- main stream: CSR build
    int nInt4 = (N + 3) / 4;
    zero_kernel<<<(nInt4 + 255) / 256, 256>>>((float4*)gdeg, nInt4);
    degree_kernel<<<(E + 255) / 256, 256>>>(dst, gdeg, E);
    int nb = (N + 1023) / 1024;
    scan1_kernel<<<nb, 256>>>(gdeg, gexcl, gbsum, N);

    // ---- side stream: encoders (fp16 features only)
    encode_kernel<48><<<(n_com + 127) / 128, 256, 0, s2>>>(
        x_com, W_com, b_com, gxh + (size_t)n_ind * HD, n_com);
    encode_kernel<32><<<(n_ind + 127) / 128, 256, 0, s2>>>(
        x_ind, W_ind, b_ind, gxh, n_ind);
    encode_kernel<24><<<(n_tru + 127) / 128, 256, 0, s2>>>(
        x_tru, W_tru, b_tru, gxh + (size_t)(n_ind + n_com) * HD, n_tru);
    cudaEventRecord(evEnc, s2);

    // ---- main stream: rest of CSR build
    scan2_kernel<<<1, 512>>>(gbsum, nb);
    scan3_kernel<<<(N + 255) / 256, 256>>>(gexcl, gbsum, goff, gcur, N, E);
    bucket_kernel<<<(E + 255) / 256, 256>>>(src, dst, gcur, gnbr, E);

    // ---- join: layers need both encoders and CSR
    cudaStreamWaitEvent(0, evEnc, 0);

    // ---- SAGE layer 1: gather fp16 -> fp16 mean; combine (fp16 in/out) -> g_yh
    agg_kernel<<<(N * 32 + 255) / 256, 256>>>(gxh, goff, gnbr, gaggh, N);
    sage_combine_kernel<<<(N + 127) / 128, 256>>>(gxh, gaggh, W1l, W1r, b1,
                                                  nullptr, gyh, N);

    // ---- SAGE layer 2: combine writes fp32 for the classifier
    agg_kernel<<<(N * 32 + 255) / 256, 256>>>(gyh, goff, gnbr, gaggh, N);
    sage_combine_kernel<<<(N + 127) / 128, 256>>>(gyh, gaggh, W2l, W2r, b2,
                                                  gx, nullptr, N);

    // ---- classifier -> d_out
    classify_kernel<<<(N + 255) / 256, 256>>>(gx, Wc1, bc1, Wc2, bc2, (float*)d_out, N);
}